// round 6
// baseline (speedup 1.0000x reference)
#include <cuda_runtime.h>
#include <cstdint>

// Problem shape (fixed by reference): B=32, S=128, V=32000
// loss = -sum_{b,s} prob[b,s,target[b,s]] * reward[b]
//
// Latency-bound: 4096 scattered gathers -> 1 scalar. R2-R5 post-mortem:
// kernel time bounces 5.4-6.8us regardless of tail protocol; the untested
// structural term is the same-address L2 atomic convoy (128 REDs + 128
// tickets, ~27cyc/op serialized). This version quarters it:
//   32 CTAs x 32 threads (1 warp/SM), 4 items/thread via LDG.128 targets +
//   4 parallel gathers; 32 REDs + 32 acq_rel tickets total.

#define B_ 32
#define S_ 128
#define V_ 32000
#define N_ (B_ * S_)      // 4096
#define NCTA_ 32
#define NTHR_ 32
#define NWARPS_ (NCTA_ * NTHR_ / 32)   // 32; 2^32 % 32 == 0 -> wrap-safe

__device__ float        g_sum    = 0.0f;  // read+reset by last warp each launch
__device__ unsigned int g_ticket = 0;     // wraps across replays

__global__ void rl_loss_kernel(const float* __restrict__ prob,
                               const int* __restrict__ target,
                               const float* __restrict__ reward,
                               float* __restrict__ out) {
    int gid = blockIdx.x * NTHR_ + threadIdx.x;      // 0..1023
    int j0  = gid << 2;                              // first of 4 items

    // b is constant across the 4 items (4 | 128) and uniform per warp.
    float r = __ldg(&reward[gid >> 5]);

    // One vectorized load of 4 targets, then 4 independent gathers (MLP=4).
    int4 t4 = __ldg((const int4*)(target + j0));
    float v0 = __ldg(&prob[(long long)(j0 + 0) * V_ + t4.x]);
    float v1 = __ldg(&prob[(long long)(j0 + 1) * V_ + t4.y]);
    float v2 = __ldg(&prob[(long long)(j0 + 2) * V_ + t4.z]);
    float v3 = __ldg(&prob[(long long)(j0 + 3) * V_ + t4.w]);

    float x = ((v0 + v1) + (v2 + v3)) * r;

    // warp tree-reduce (5 shuffles)
    #pragma unroll
    for (int off = 16; off > 0; off >>= 1)
        x += __shfl_xor_sync(0xFFFFFFFFu, x, off);

    if (threadIdx.x == 0) {
        // Relaxed accumulate, no return (REDG).
        asm volatile("red.relaxed.gpu.global.add.f32 [%0], %1;"
                     :: "l"(&g_sum), "f"(x) : "memory");

        // acq_rel ticket: release orders our RED before the increment;
        // acquire makes all earlier warps' REDs visible to the last arriver.
        unsigned int old;
        asm volatile("atom.acq_rel.gpu.global.add.u32 %0, [%1], 1;"
                     : "=r"(old) : "l"(&g_ticket) : "memory");

        if ((old & (NWARPS_ - 1)) == NWARPS_ - 1) {
            // Read the completed sum AND reset it for the next replay.
            float tot = atomicExch(&g_sum, 0.0f);
            *out = -tot;                     // overwrites harness poison
        }
    }
}

extern "C" void kernel_launch(void* const* d_in, const int* in_sizes, int n_in,
                              void* d_out, int out_size) {
    // Identify inputs by element count, robust to ordering:
    //   prob: B*S*V = 131,072,000   target: B*S = 4096   reward: B = 32
    const float* prob   = nullptr;
    const int*   target = nullptr;
    const float* reward = nullptr;
    for (int k = 0; k < n_in; k++) {
        if (in_sizes[k] == N_ * V_)      prob   = (const float*)d_in[k];
        else if (in_sizes[k] == N_)      target = (const int*)d_in[k];
        else if (in_sizes[k] == B_)      reward = (const float*)d_in[k];
    }
    float* out = (float*)d_out;

    // Single graph node: 32 CTAs x 32 threads, 4 gathers per thread.
    rl_loss_kernel<<<NCTA_, NTHR_>>>(prob, target, reward, out);
}

// round 7
// speedup vs baseline: 1.2639x; 1.2639x over previous
#include <cuda_runtime.h>
#include <cstdint>

// Problem shape (fixed by reference): B=32, S=128, V=32000
// loss = -sum_{b,s} prob[b,s,target[b,s]] * reward[b]
//
// Latency-bound: 4096 scattered gathers -> 1 scalar. Model after R2-R6:
// kernel floor ~5.4us = launch ramp (~3us) + one 2-deep L2-warm load chain
// + tail. Best geometry = 32x128, one gather/thread (R2/R5). R6 (1 warp/SM,
// ILP-4) regressed: no warp-level latency hiding. This round: keep the
// winning geometry, add 32-bit gather addressing (index < 2^31 -> no
// IMAD.WIDE chain), CTA-level smem combine (tail = 32 RED+ticket pairs),
// proven wrap-ticket + atomicExch read+reset finalize. Single graph node.

#define B_ 32
#define S_ 128
#define V_ 32000
#define N_ (B_ * S_)      // 4096
#define NCTA_ 32
#define NTHR_ 128
// 2^32 % NCTA_ == 0 -> ticket wraps consistently across unlimited replays

__device__ float        g_sum    = 0.0f;  // read+reset by last CTA each launch
__device__ unsigned int g_ticket = 0;     // wraps across replays

__global__ void __launch_bounds__(NTHR_, 1)
rl_loss_kernel(const float* __restrict__ prob,
               const int* __restrict__ target,
               const float* __restrict__ reward,
               float* __restrict__ out) {
    __shared__ float s_warp[NTHR_ / 32];

    int i = blockIdx.x * NTHR_ + threadIdx.x;   // 0..4095
    float r = __ldg(&reward[i >> 7]);           // independent; issues first
    int t = __ldg(&target[i]);                  // coalesced int32
    // 32-bit index: max = 4095*32000 + 31999 = 131,071,999 < 2^31
    float v = __ldg(&prob[i * V_ + t]);         // scattered gather (L2-warm)
    float x = v * r;

    // warp tree-reduce (5 shuffles)
    #pragma unroll
    for (int off = 16; off > 0; off >>= 1)
        x += __shfl_xor_sync(0xFFFFFFFFu, x, off);

    if ((threadIdx.x & 31) == 0) s_warp[threadIdx.x >> 5] = x;
    __syncthreads();

    if (threadIdx.x == 0) {
        float p = (s_warp[0] + s_warp[1]) + (s_warp[2] + s_warp[3]);

        // Relaxed accumulate, no return (REDG).
        asm volatile("red.relaxed.gpu.global.add.f32 [%0], %1;"
                     :: "l"(&g_sum), "f"(p) : "memory");

        // acq_rel ticket: release orders our RED before the increment;
        // acquire makes all earlier CTAs' REDs visible to the last arriver.
        unsigned int old;
        asm volatile("atom.acq_rel.gpu.global.add.u32 %0, [%1], 1;"
                     : "=r"(old) : "l"(&g_ticket) : "memory");

        if ((old & (NCTA_ - 1)) == NCTA_ - 1) {
            // Read the completed sum AND reset it for the next replay.
            float tot = atomicExch(&g_sum, 0.0f);
            *out = -tot;                 // overwrites harness poison
        }
    }
}

extern "C" void kernel_launch(void* const* d_in, const int* in_sizes, int n_in,
                              void* d_out, int out_size) {
    // Identify inputs by element count, robust to ordering:
    //   prob: B*S*V = 131,072,000   target: B*S = 4096   reward: B = 32
    const float* prob   = nullptr;
    const int*   target = nullptr;
    const float* reward = nullptr;
    for (int k = 0; k < n_in; k++) {
        if (in_sizes[k] == N_ * V_)      prob   = (const float*)d_in[k];
        else if (in_sizes[k] == N_)      target = (const int*)d_in[k];
        else if (in_sizes[k] == B_)      reward = (const float*)d_in[k];
    }
    float* out = (float*)d_out;

    // Single graph node: 32 CTAs x 128 threads, one gather each.
    rl_loss_kernel<<<NCTA_, NTHR_>>>(prob, target, reward, out);
}

// round 8
// speedup vs baseline: 1.2698x; 1.0047x over previous
#include <cuda_runtime.h>
#include <cstdint>

// Problem shape (fixed by reference): B=32, S=128, V=32000
// loss = -sum_{b,s} prob[b,s,target[b,s]] * reward[b]
//
// Latency-bound: 4096 scattered gathers -> 1 scalar; geometry settled at
// 32 CTAs x 128 thr (best across R2-R7). This round collapses the global
// rendezvous (RED + acq_rel ticket + atomicExch = 3 L2 round-trips) into a
// SINGLE relaxed 64-bit atomicAdd: high 32 bits = fixed-point sum (x2^20),
// low 32 bits = arrival count. The 32nd arriver has the complete total
// in-register from the atomic's return value -> convert, STG -out, then
// fire-and-forget exact integer subtract resets g_acc to 0 for the next
// graph replay (kernel-boundary fence orders it before the next launch).
// No acquire/release anywhere: the value rides inside the atomic itself.

#define B_ 32
#define S_ 128
#define V_ 32000
#define N_ (B_ * S_)      // 4096
#define NCTA_ 32
#define NTHR_ 128
#define FIX_SCALE 1048576.0f          // 2^20
#define FIX_INV  (-9.5367431640625e-07f)  // -(2^-20), fused negate

__device__ unsigned long long g_acc = 0ULL;  // (fixed_sum<<32) | arrival_count

__global__ void __launch_bounds__(NTHR_, 1)
rl_loss_kernel(const float* __restrict__ prob,
               const int* __restrict__ target,
               const float* __restrict__ reward,
               float* __restrict__ out) {
    __shared__ float s_warp[NTHR_ / 32];

    int i = blockIdx.x * NTHR_ + threadIdx.x;   // 0..4095
    float r = __ldg(&reward[i >> 7]);           // independent; issues first
    int t = __ldg(&target[i]);                  // coalesced int32
    // 32-bit index: max = 4095*32000 + 31999 = 131,071,999 < 2^31
    float v = __ldg(&prob[i * V_ + t]);         // scattered gather (L2-warm)
    float x = v * r;

    // warp tree-reduce (5 shuffles)
    #pragma unroll
    for (int off = 16; off > 0; off >>= 1)
        x += __shfl_xor_sync(0xFFFFFFFFu, x, off);

    if ((threadIdx.x & 31) == 0) s_warp[threadIdx.x >> 5] = x;
    __syncthreads();

    if (threadIdx.x == 0) {
        float p = (s_warp[0] + s_warp[1]) + (s_warp[2] + s_warp[3]);

        // Quantize CTA partial (p in [0,128)) to fixed-point: < 2^27.
        unsigned int fx = (unsigned int)__float2uint_rn(p * FIX_SCALE);
        unsigned long long pack = ((unsigned long long)fx << 32) | 1ULL;

        // Single relaxed atomic carries both sum and arrival count.
        unsigned long long old = atomicAdd(&g_acc, pack);

        if ((old & 0xFFFFFFFFULL) == (unsigned long long)(NCTA_ - 1)) {
            unsigned long long total = old + pack;   // complete, in-register
            unsigned int fixed_tot = (unsigned int)(total >> 32);
            *out = (float)fixed_tot * FIX_INV;       // -sum; overwrites poison
            // Exact integer reset to 0 for next replay (off critical path;
            // committed by the kernel-boundary fence before the next launch).
            atomicAdd(&g_acc, (unsigned long long)(0ULL - total));
        }
    }
}

extern "C" void kernel_launch(void* const* d_in, const int* in_sizes, int n_in,
                              void* d_out, int out_size) {
    // Identify inputs by element count, robust to ordering:
    //   prob: B*S*V = 131,072,000   target: B*S = 4096   reward: B = 32
    const float* prob   = nullptr;
    const int*   target = nullptr;
    const float* reward = nullptr;
    for (int k = 0; k < n_in; k++) {
        if (in_sizes[k] == N_ * V_)      prob   = (const float*)d_in[k];
        else if (in_sizes[k] == N_)      target = (const int*)d_in[k];
        else if (in_sizes[k] == B_)      reward = (const float*)d_in[k];
    }
    float* out = (float*)d_out;

    // Single graph node: 32 CTAs x 128 threads, one gather each.
    rl_loss_kernel<<<NCTA_, NTHR_>>>(prob, target, reward, out);
}